// round 13
// baseline (speedup 1.0000x reference)
#include <cuda_runtime.h>
#include <cuda_fp16.h>
#include <cstdint>

#define ZD            16
#define KN            64
#define NTHREADS      256
#define WARPS         8
#define TPW           8                        // iterations per warp (32 rows each)
#define ROWS_PER_WARP (TPW * 32)               // 256
#define ROWS_PER_CTA  (WARPS * ROWS_PER_WARP)  // 2048

#define STAGES        4
#define STAGE_BYTES   2048                     // 32 rows x 64 B per warp
#define SMEM_DYN      (STAGES * WARPS * STAGE_BYTES)   // 64 KB

// ---- helpers ---------------------------------------------------------------
__device__ __forceinline__ uint32_t pack_h2(float lo, float hi) {
    uint32_t r;
    asm("cvt.rn.f16x2.f32 %0, %1, %2;" : "=r"(r) : "f"(hi), "f"(lo));
    return r;
}
__device__ __forceinline__ float tanh_a(float x) {
    float r;
    asm("tanh.approx.f32 %0, %1;" : "=f"(r) : "f"(x));
    return r;
}
__device__ __forceinline__ uint32_t smem_u32(const void* p) {
    uint32_t a;
    asm("{ .reg .u64 t; cvta.to.shared.u64 t, %1; cvt.u32.u64 %0, t; }" : "=r"(a) : "l"(p));
    return a;
}
__device__ __forceinline__ void cp_async16(uint32_t dst, const void* src) {
    asm volatile("cp.async.cg.shared.global [%0], [%1], 16;" :: "r"(dst), "l"(src));
}
#define CP_COMMIT() asm volatile("cp.async.commit_group;" ::: "memory")
#define CP_WAIT2()  asm volatile("cp.async.wait_group 2;" ::: "memory")

__device__ __forceinline__ float2 lds64(uint32_t addr) {
    float2 v;
    asm volatile("ld.shared.v2.f32 {%0, %1}, [%2];" : "=f"(v.x), "=f"(v.y) : "r"(addr));
    return v;
}
// fp16 MMA, fp32 accum, C preloaded with {dk0, dk1, dk0, dk1} (free dk add)
__device__ __forceinline__ void mma_h_init(float* d, const uint32_t* a,
                                           uint32_t b0, uint32_t b1,
                                           float c0, float c1) {
    asm("mma.sync.aligned.m16n8k16.row.col.f32.f16.f16.f32 "
        "{%0,%1,%2,%3}, {%4,%5,%6,%7}, {%8,%9}, {%10,%11,%12,%13};"
        : "=f"(d[0]), "=f"(d[1]), "=f"(d[2]), "=f"(d[3])
        : "r"(a[0]), "r"(a[1]), "r"(a[2]), "r"(a[3]),
          "r"(b0), "r"(b1),
          "f"(c0), "f"(c1), "f"(c0), "f"(c1));
}

// ---- main kernel -----------------------------------------------------------
__global__ void __launch_bounds__(NTHREADS) mave_mma(
    const float* __restrict__ z, const float* __restrict__ a0p,
    const float* __restrict__ bkp, const float* __restrict__ ck,
    const float* __restrict__ dkp, float* __restrict__ out)
{
    extern __shared__ char zstage[];          // [STAGES][WARPS][2048]
    __shared__ float4 sdb[KN / 2];            // {dk0,bk0,dk1,bk1} per column pair

    const int tid  = threadIdx.x;
    const int wid  = tid >> 5;
    const int lane = tid & 31;
    const int quad = lane >> 2;     // 0..7
    const int qid  = lane & 3;      // 0..3

    if (tid < KN / 2) {
        float4 v;
        v.x = dkp[2 * tid];     v.y = bkp[2 * tid];
        v.z = dkp[2 * tid + 1]; v.w = bkp[2 * tid + 1];
        sdb[tid] = v;
    }
    __syncthreads();
    const float a0 = a0p[0];

    // constant B fragments: ck as plain fp16, 8 n-tiles, 16 regs
    uint32_t bh[8][2];
    #pragma unroll
    for (int j = 0; j < 8; ++j) {
        const float* cr = ck + (j * 8 + quad) * ZD + qid * 2;
        float2 g0 = *reinterpret_cast<const float2*>(cr);
        float2 g1 = *reinterpret_cast<const float2*>(cr + 8);
        bh[j][0] = pack_h2(g0.x, g0.y);
        bh[j][1] = pack_h2(g1.x, g1.y);
    }

    const long warp_base = (long)blockIdx.x * ROWS_PER_CTA + (long)wid * ROWS_PER_WARP;
    const char* zbytes = reinterpret_cast<const char*>(z) + warp_base * (ZD * 4);

    // per-warp stage ring base addresses (smem u32)
    const uint32_t ring = smem_u32(zstage) + (uint32_t)wid * STAGE_BYTES;
    // stage s base = ring + s * (WARPS*STAGE_BYTES)
    #define STAGE_ADDR(s) (ring + (uint32_t)(s) * (WARPS * STAGE_BYTES))

    // issue one stage copy: 32 rows x 64 B = 2048 B; 4 chunks of 16 B per lane
    #define ISSUE_STAGE(blk, s) do {                                          \
        const char* src = zbytes + (long)(blk) * STAGE_BYTES;                 \
        uint32_t dst = STAGE_ADDR(s);                                         \
        cp_async16(dst + lane * 16,        src + lane * 16);                  \
        cp_async16(dst + 512 + lane * 16,  src + 512 + lane * 16);            \
        cp_async16(dst + 1024 + lane * 16, src + 1024 + lane * 16);           \
        cp_async16(dst + 1536 + lane * 16, src + 1536 + lane * 16);           \
    } while (0)

    // prologue: stages 0..2
    ISSUE_STAGE(0, 0); CP_COMMIT();
    ISSUE_STAGE(1, 1); CP_COMMIT();
    ISSUE_STAGE(2, 2); CP_COMMIT();

    // fragment offsets within a stage (row-major, 64 B rows):
    const uint32_t fo = (uint32_t)quad * 64 + (uint32_t)qid * 8;

    #pragma unroll 1
    for (int blk = 0; blk < TPW; ++blk) {
        CP_WAIT2();   // group 'blk' complete

        const uint32_t sb = STAGE_ADDR(blk & (STAGES - 1));
        // block A: rows quad, quad+8 ; block B: rows quad+16, quad+24
        float2 pA0 = lds64(sb + fo);                // (quad,    k qid*2)
        float2 pA1 = lds64(sb + fo + 8 * 64);       // (quad+8,  k qid*2)
        float2 pA2 = lds64(sb + fo + 32);           // (quad,    k qid*2+8)
        float2 pA3 = lds64(sb + fo + 8 * 64 + 32);
        float2 pB0 = lds64(sb + fo + 16 * 64);
        float2 pB1 = lds64(sb + fo + 24 * 64);
        float2 pB2 = lds64(sb + fo + 16 * 64 + 32);
        float2 pB3 = lds64(sb + fo + 24 * 64 + 32);

        uint32_t aA[4], aB[4];
        aA[0] = pack_h2(pA0.x, pA0.y);
        aA[1] = pack_h2(pA1.x, pA1.y);
        aA[2] = pack_h2(pA2.x, pA2.y);
        aA[3] = pack_h2(pA3.x, pA3.y);
        aB[0] = pack_h2(pB0.x, pB0.y);
        aB[1] = pack_h2(pB1.x, pB1.y);
        aB[2] = pack_h2(pB2.x, pB2.y);
        aB[3] = pack_h2(pB3.x, pB3.y);

        // refill: stage blk+3 (always commit to keep group counting aligned)
        if (blk + 3 < TPW) {
            ISSUE_STAGE(blk + 3, (blk + 3) & (STAGES - 1));
        }
        CP_COMMIT();

        float accA0 = 0.f, accA1 = 0.f, accA2 = 0.f, accA3 = 0.f;
        float accB0 = 0.f, accB1 = 0.f, accB2 = 0.f, accB3 = 0.f;

        #pragma unroll
        for (int j = 0; j < 8; ++j) {
            float4 q = sdb[j * 4 + qid];   // LDS.128 broadcast, serves both blocks
            float dA[4], dB[4];
            mma_h_init(dA, aA, bh[j][0], bh[j][1], q.x, q.z);  // z*c + dk
            mma_h_init(dB, aB, bh[j][0], bh[j][1], q.x, q.z);

            accA0 = fmaf(tanh_a(dA[0]), q.y, accA0);
            accA1 = fmaf(tanh_a(dA[1]), q.w, accA1);
            accA2 = fmaf(tanh_a(dA[2]), q.y, accA2);
            accA3 = fmaf(tanh_a(dA[3]), q.w, accA3);
            accB0 = fmaf(tanh_a(dB[0]), q.y, accB0);
            accB1 = fmaf(tanh_a(dB[1]), q.w, accB1);
            accB2 = fmaf(tanh_a(dB[2]), q.y, accB2);
            accB3 = fmaf(tanh_a(dB[3]), q.w, accB3);
        }

        float rA0 = accA0 + accA1, rA1 = accA2 + accA3;   // rows quad, quad+8
        float rB0 = accB0 + accB1, rB1 = accB2 + accB3;   // rows quad+16, quad+24
        rA0 += __shfl_xor_sync(0xFFFFFFFFu, rA0, 1);
        rA0 += __shfl_xor_sync(0xFFFFFFFFu, rA0, 2);
        rA1 += __shfl_xor_sync(0xFFFFFFFFu, rA1, 1);
        rA1 += __shfl_xor_sync(0xFFFFFFFFu, rA1, 2);
        rB0 += __shfl_xor_sync(0xFFFFFFFFu, rB0, 1);
        rB0 += __shfl_xor_sync(0xFFFFFFFFu, rB0, 2);
        rB1 += __shfl_xor_sync(0xFFFFFFFFu, rB1, 1);
        rB1 += __shfl_xor_sync(0xFFFFFFFFu, rB1, 2);

        if (qid == 0) {
            const long r0 = warp_base + (long)blk * 32 + quad;
            out[r0]      = a0 + rA0;
            out[r0 + 8]  = a0 + rA1;
            out[r0 + 16] = a0 + rB0;
            out[r0 + 24] = a0 + rB1;
        }
    }
    #undef ISSUE_STAGE
    #undef STAGE_ADDR
}

// ---- scalar tail (unused when B % 2048 == 0; B = 2M is) --------------------
__global__ void mave_tail(
    const float* __restrict__ z, const float* __restrict__ a0p,
    const float* __restrict__ bk, const float* __restrict__ ck,
    const float* __restrict__ dk, float* __restrict__ out,
    long start, long Btot)
{
    long row = start + (long)blockIdx.x * blockDim.x + threadIdx.x;
    if (row >= Btot) return;
    const float* zr = z + row * ZD;
    float zv[ZD];
    #pragma unroll
    for (int i = 0; i < ZD; ++i) zv[i] = zr[i];
    float acc = a0p[0];
    for (int k = 0; k < KN; ++k) {
        float h = dk[k];
        #pragma unroll
        for (int zi = 0; zi < ZD; ++zi) h = fmaf(ck[k * ZD + zi], zv[zi], h);
        acc = fmaf(bk[k], tanh_a(h), acc);
    }
    out[row] = acc;
}

extern "C" void kernel_launch(void* const* d_in, const int* in_sizes, int n_in,
                              void* d_out, int out_size) {
    const float* z  = (const float*)d_in[0];
    const float* a0 = (const float*)d_in[1];
    const float* bk = (const float*)d_in[2];
    const float* ck = (const float*)d_in[3];
    const float* dk = (const float*)d_in[4];
    float* out = (float*)d_out;

    static int smem_set = 0;
    if (!smem_set) {
        cudaFuncSetAttribute(mave_mma, cudaFuncAttributeMaxDynamicSharedMemorySize,
                             SMEM_DYN);
        smem_set = 1;
    }

    const long B = (long)in_sizes[0] / ZD;
    const long nfull = B / ROWS_PER_CTA;

    if (nfull > 0) {
        mave_mma<<<(int)nfull, NTHREADS, SMEM_DYN>>>(z, a0, bk, ck, dk, out);
    }
    const long rem = B - nfull * ROWS_PER_CTA;
    if (rem > 0) {
        mave_tail<<<(int)((rem + 255) / 256), 256>>>(z, a0, bk, ck, dk, out,
                                                     nfull * ROWS_PER_CTA, B);
    }
}

// round 14
// speedup vs baseline: 1.0062x; 1.0062x over previous
#include <cuda_runtime.h>
#include <cuda_fp16.h>
#include <cstdint>

#define ZD            16
#define KN            64
#define NTHREADS      256
#define WARPS         8
#define TPW           8                        // iterations per warp (32 rows each)
#define ROWS_PER_WARP (TPW * 32)               // 256
#define ROWS_PER_CTA  (WARPS * ROWS_PER_WARP)  // 2048

#define STAGES        4
#define STAGE_BYTES   2048                     // 32 rows x 64 B per warp
#define SMEM_DYN      (STAGES * WARPS * STAGE_BYTES)   // 64 KB

// ---- helpers ---------------------------------------------------------------
__device__ __forceinline__ uint32_t pack_h2(float lo, float hi) {
    uint32_t r;
    asm("cvt.rn.f16x2.f32 %0, %1, %2;" : "=r"(r) : "f"(hi), "f"(lo));
    return r;
}
__device__ __forceinline__ uint32_t tanh2(uint32_t h2) {
    uint32_t r;
    asm("tanh.approx.f16x2 %0, %1;" : "=r"(r) : "r"(h2));
    return r;
}
__device__ __forceinline__ __half2 u2h2(uint32_t u) {
    return *reinterpret_cast<__half2*>(&u);
}
__device__ __forceinline__ float tanh_a(float x) {
    float r;
    asm("tanh.approx.f32 %0, %1;" : "=f"(r) : "f"(x));
    return r;
}
__device__ __forceinline__ uint32_t smem_u32(const void* p) {
    uint32_t a;
    asm("{ .reg .u64 t; cvta.to.shared.u64 t, %1; cvt.u32.u64 %0, t; }" : "=r"(a) : "l"(p));
    return a;
}
__device__ __forceinline__ void cp_async16(uint32_t dst, const void* src) {
    asm volatile("cp.async.cg.shared.global [%0], [%1], 16;" :: "r"(dst), "l"(src));
}
#define CP_COMMIT() asm volatile("cp.async.commit_group;" ::: "memory")
#define CP_WAIT2()  asm volatile("cp.async.wait_group 2;" ::: "memory")

__device__ __forceinline__ float2 lds64(uint32_t addr) {
    float2 v;
    asm volatile("ld.shared.v2.f32 {%0, %1}, [%2];" : "=f"(v.x), "=f"(v.y) : "r"(addr));
    return v;
}
// fp16 MMA, fp32 accum, C preloaded with {dk0, dk1, dk0, dk1} (free dk add)
__device__ __forceinline__ void mma_h_init(float* d, const uint32_t* a,
                                           uint32_t b0, uint32_t b1,
                                           float c0, float c1) {
    asm("mma.sync.aligned.m16n8k16.row.col.f32.f16.f16.f32 "
        "{%0,%1,%2,%3}, {%4,%5,%6,%7}, {%8,%9}, {%10,%11,%12,%13};"
        : "=f"(d[0]), "=f"(d[1]), "=f"(d[2]), "=f"(d[3])
        : "r"(a[0]), "r"(a[1]), "r"(a[2]), "r"(a[3]),
          "r"(b0), "r"(b1),
          "f"(c0), "f"(c1), "f"(c0), "f"(c1));
}

// ---- main kernel -----------------------------------------------------------
__global__ void __launch_bounds__(NTHREADS) mave_mma(
    const float* __restrict__ z, const float* __restrict__ a0p,
    const float* __restrict__ bkp, const float* __restrict__ ck,
    const float* __restrict__ dkp, float* __restrict__ out)
{
    extern __shared__ char zstage[];          // [STAGES][WARPS][2048]
    __shared__ float2 sdk[KN / 2];            // {dk0, dk1} per column pair

    const int tid  = threadIdx.x;
    const int wid  = tid >> 5;
    const int lane = tid & 31;
    const int quad = lane >> 2;     // 0..7
    const int qid  = lane & 3;      // 0..3

    if (tid < KN / 2) {
        float2 v; v.x = dkp[2 * tid]; v.y = dkp[2 * tid + 1];
        sdk[tid] = v;
    }
    __syncthreads();
    const float a0 = a0p[0];

    // constant B fragments: ck as plain fp16, 8 n-tiles, 16 regs
    uint32_t bh[8][2];
    #pragma unroll
    for (int j = 0; j < 8; ++j) {
        const float* cr = ck + (j * 8 + quad) * ZD + qid * 2;
        float2 g0 = *reinterpret_cast<const float2*>(cr);
        float2 g1 = *reinterpret_cast<const float2*>(cr + 8);
        bh[j][0] = pack_h2(g0.x, g0.y);
        bh[j][1] = pack_h2(g1.x, g1.y);
    }
    // bk as half2 per (j): {bk[c0], bk[c1]} with c0 = j*8 + qid*2
    __half2 bk2[8];
    #pragma unroll
    for (int j = 0; j < 8; ++j) {
        const float* bkr = bkp + j * 8 + qid * 2;
        bk2[j] = u2h2(pack_h2(bkr[0], bkr[1]));
    }

    const long warp_base = (long)blockIdx.x * ROWS_PER_CTA + (long)wid * ROWS_PER_WARP;
    const char* zbytes = reinterpret_cast<const char*>(z) + warp_base * (ZD * 4);

    const uint32_t ring = smem_u32(zstage) + (uint32_t)wid * STAGE_BYTES;
    #define STAGE_ADDR(s) (ring + (uint32_t)(s) * (WARPS * STAGE_BYTES))

    #define ISSUE_STAGE(blk, s) do {                                          \
        const char* src = zbytes + (long)(blk) * STAGE_BYTES;                 \
        uint32_t dst = STAGE_ADDR(s);                                         \
        cp_async16(dst + lane * 16,        src + lane * 16);                  \
        cp_async16(dst + 512 + lane * 16,  src + 512 + lane * 16);            \
        cp_async16(dst + 1024 + lane * 16, src + 1024 + lane * 16);           \
        cp_async16(dst + 1536 + lane * 16, src + 1536 + lane * 16);           \
    } while (0)

    // prologue: stages 0..2
    ISSUE_STAGE(0, 0); CP_COMMIT();
    ISSUE_STAGE(1, 1); CP_COMMIT();
    ISSUE_STAGE(2, 2); CP_COMMIT();

    const uint32_t fo = (uint32_t)quad * 64 + (uint32_t)qid * 8;

    #pragma unroll 1
    for (int blk = 0; blk < TPW; ++blk) {
        CP_WAIT2();   // group 'blk' complete

        const uint32_t sb = STAGE_ADDR(blk & (STAGES - 1));
        float2 pA0 = lds64(sb + fo);                // (quad,    k qid*2)
        float2 pA1 = lds64(sb + fo + 8 * 64);       // (quad+8,  k qid*2)
        float2 pA2 = lds64(sb + fo + 32);           // (quad,    k qid*2+8)
        float2 pA3 = lds64(sb + fo + 8 * 64 + 32);
        float2 pB0 = lds64(sb + fo + 16 * 64);
        float2 pB1 = lds64(sb + fo + 24 * 64);
        float2 pB2 = lds64(sb + fo + 16 * 64 + 32);
        float2 pB3 = lds64(sb + fo + 24 * 64 + 32);

        uint32_t aA[4], aB[4];
        aA[0] = pack_h2(pA0.x, pA0.y);
        aA[1] = pack_h2(pA1.x, pA1.y);
        aA[2] = pack_h2(pA2.x, pA2.y);
        aA[3] = pack_h2(pA3.x, pA3.y);
        aB[0] = pack_h2(pB0.x, pB0.y);
        aB[1] = pack_h2(pB1.x, pB1.y);
        aB[2] = pack_h2(pB2.x, pB2.y);
        aB[3] = pack_h2(pB3.x, pB3.y);

        if (blk + 3 < TPW) {
            ISSUE_STAGE(blk + 3, (blk + 3) & (STAGES - 1));
        }
        CP_COMMIT();

        // half2 accumulators: 2 chains per row (length-4 hfma2 chains)
        const __half2 zh2 = __float2half2_rn(0.f);
        __half2 hA0[2] = {zh2, zh2}, hA1[2] = {zh2, zh2};
        __half2 hB0[2] = {zh2, zh2}, hB1[2] = {zh2, zh2};

        #pragma unroll
        for (int j = 0; j < 8; ++j) {
            float2 qd = sdk[j * 4 + qid];   // {dk0, dk1}, LDS.64 broadcast
            float dA[4], dB[4];
            mma_h_init(dA, aA, bh[j][0], bh[j][1], qd.x, qd.y);  // z*c + dk
            mma_h_init(dB, aB, bh[j][0], bh[j][1], qd.x, qd.y);

            const int p = j & 1;
            hA0[p] = __hfma2(u2h2(tanh2(pack_h2(dA[0], dA[1]))), bk2[j], hA0[p]);
            hA1[p] = __hfma2(u2h2(tanh2(pack_h2(dA[2], dA[3]))), bk2[j], hA1[p]);
            hB0[p] = __hfma2(u2h2(tanh2(pack_h2(dB[0], dB[1]))), bk2[j], hB0[p]);
            hB1[p] = __hfma2(u2h2(tanh2(pack_h2(dB[2], dB[3]))), bk2[j], hB1[p]);
        }

        // fp32 finish: convert chains, sum halves
        float2 fA0 = __half22float2(hA0[0]), fA0b = __half22float2(hA0[1]);
        float2 fA1 = __half22float2(hA1[0]), fA1b = __half22float2(hA1[1]);
        float2 fB0 = __half22float2(hB0[0]), fB0b = __half22float2(hB0[1]);
        float2 fB1 = __half22float2(hB1[0]), fB1b = __half22float2(hB1[1]);
        float rA0 = (fA0.x + fA0.y) + (fA0b.x + fA0b.y);
        float rA1 = (fA1.x + fA1.y) + (fA1b.x + fA1b.y);
        float rB0 = (fB0.x + fB0.y) + (fB0b.x + fB0b.y);
        float rB1 = (fB1.x + fB1.y) + (fB1b.x + fB1b.y);

        rA0 += __shfl_xor_sync(0xFFFFFFFFu, rA0, 1);
        rA0 += __shfl_xor_sync(0xFFFFFFFFu, rA0, 2);
        rA1 += __shfl_xor_sync(0xFFFFFFFFu, rA1, 1);
        rA1 += __shfl_xor_sync(0xFFFFFFFFu, rA1, 2);
        rB0 += __shfl_xor_sync(0xFFFFFFFFu, rB0, 1);
        rB0 += __shfl_xor_sync(0xFFFFFFFFu, rB0, 2);
        rB1 += __shfl_xor_sync(0xFFFFFFFFu, rB1, 1);
        rB1 += __shfl_xor_sync(0xFFFFFFFFu, rB1, 2);

        if (qid == 0) {
            const long r0 = warp_base + (long)blk * 32 + quad;
            out[r0]      = a0 + rA0;
            out[r0 + 8]  = a0 + rA1;
            out[r0 + 16] = a0 + rB0;
            out[r0 + 24] = a0 + rB1;
        }
    }
    #undef ISSUE_STAGE
    #undef STAGE_ADDR
}

// ---- scalar tail (unused when B % 2048 == 0; B = 2M is) --------------------
__global__ void mave_tail(
    const float* __restrict__ z, const float* __restrict__ a0p,
    const float* __restrict__ bk, const float* __restrict__ ck,
    const float* __restrict__ dk, float* __restrict__ out,
    long start, long Btot)
{
    long row = start + (long)blockIdx.x * blockDim.x + threadIdx.x;
    if (row >= Btot) return;
    const float* zr = z + row * ZD;
    float zv[ZD];
    #pragma unroll
    for (int i = 0; i < ZD; ++i) zv[i] = zr[i];
    float acc = a0p[0];
    for (int k = 0; k < KN; ++k) {
        float h = dk[k];
        #pragma unroll
        for (int zi = 0; zi < ZD; ++zi) h = fmaf(ck[k * ZD + zi], zv[zi], h);
        acc = fmaf(bk[k], tanh_a(h), acc);
    }
    out[row] = acc;
}

extern "C" void kernel_launch(void* const* d_in, const int* in_sizes, int n_in,
                              void* d_out, int out_size) {
    const float* z  = (const float*)d_in[0];
    const float* a0 = (const float*)d_in[1];
    const float* bk = (const float*)d_in[2];
    const float* ck = (const float*)d_in[3];
    const float* dk = (const float*)d_in[4];
    float* out = (float*)d_out;

    static int smem_set = 0;
    if (!smem_set) {
        cudaFuncSetAttribute(mave_mma, cudaFuncAttributeMaxDynamicSharedMemorySize,
                             SMEM_DYN);
        smem_set = 1;
    }

    const long B = (long)in_sizes[0] / ZD;
    const long nfull = B / ROWS_PER_CTA;

    if (nfull > 0) {
        mave_mma<<<(int)nfull, NTHREADS, SMEM_DYN>>>(z, a0, bk, ck, dk, out);
    }
    const long rem = B - nfull * ROWS_PER_CTA;
    if (rem > 0) {
        mave_tail<<<(int)((rem + 255) / 256), 256>>>(z, a0, bk, ck, dk, out,
                                                     nfull * ROWS_PER_CTA, B);
    }
}